// round 9
// baseline (speedup 1.0000x reference)
#include <cuda_runtime.h>
#include <cuda_bf16.h>

// out[b, i*64 + j] = x[b, i] * W[i, j]
// B=8192, L=100, E=64. Output row = 6400 floats = 1600 float4.
//
// R8: identical to R7 except plain write-back stores instead of __stcs.
// The 210MB output is re-written every harness replay into the SAME buffer;
// with default policy a large fraction stays dirty-resident in the 126MB L2
// across replays and never costs DRAM bandwidth. The .cs hint was forcing
// early eviction/writeback of exactly those lines.
//
// Structure: thread <-> one float4 column (5 col-groups x 320 threads),
// block owns 16 CONTIGUOUS batch rows -> all 16 x-loads and 16 STG.128 use
// one base register + compile-time immediate offsets (row stride 25.6KB).

#define L_DIM    100
#define ROW_F4   1600        // 6400 floats / 4
#define THREADS  320
#define COLBLKS  5           // 5 * 320 = 1600 float4 per row
#define UNROLL   16
#define RGROUPS  (8192 / UNROLL)   // 512 row-groups

__global__ __launch_bounds__(THREADS)
void chem_embed_kernel(const float* __restrict__ x,
                       const float* __restrict__ W,
                       float* __restrict__ out)
{
    const int blk = blockIdx.x;            // [0, 5*512)
    const int cb  = blk % COLBLKS;         // column-group
    const int g   = blk / COLBLKS;         // row-group, [0,512)
    const int b0  = g * UNROLL;            // first batch row of this block

    const int r = cb * THREADS + threadIdx.x;   // float4 column, [0,1600)
    const int i = r >> 4;                       // position index (16 float4 each)

    const float4 w4 = __ldg(&((const float4*)W)[r]);

    // 16 independent x loads; single base, immediate offsets u*L_DIM.
    const float* __restrict__ xb = x + (long long)b0 * L_DIM + i;
    float xv[UNROLL];
#pragma unroll
    for (int u = 0; u < UNROLL; u++)
        xv[u] = __ldg(xb + u * L_DIM);

    // 16 independent write-back STG.128; single base, immediate offsets u*ROW_F4.
    float4* __restrict__ ob = ((float4*)out) + (long long)b0 * ROW_F4 + r;
#pragma unroll
    for (int u = 0; u < UNROLL; u++) {
        float4 o;
        o.x = xv[u] * w4.x;
        o.y = xv[u] * w4.y;
        o.z = xv[u] * w4.z;
        o.w = xv[u] * w4.w;
        ob[u * ROW_F4] = o;
    }
}

extern "C" void kernel_launch(void* const* d_in, const int* in_sizes, int n_in,
                              void* d_out, int out_size)
{
    const float* x = (const float*)d_in[0];   // [8192, 100]
    const float* W = (const float*)d_in[1];   // [100, 64]
    float* out = (float*)d_out;               // [8192, 1, 6400]

    dim3 grid(COLBLKS * RGROUPS);             // 2560 blocks
    dim3 block(THREADS);
    chem_embed_kernel<<<grid, block>>>(x, W, out);
}

// round 10
// speedup vs baseline: 1.0330x; 1.0330x over previous
#include <cuda_runtime.h>
#include <cuda_bf16.h>

// out[b, i*64 + j] = x[b, i] * W[i, j]
// B=8192, L=100, E=64. Output row = 6400 floats = 1600 float4.
//
// R9: all confirmed winners together, single-wave persistent.
//  - __stcs streaming stores (R8 proved removing them costs ~4us)
//  - contiguous 8 rows per work item -> base reg + immediate offsets
//  - UNROLL 8 (R6's best MLP/occupancy trade)
//  - grid = 148*6 = 888 blocks, grid-stride over 5120 work items:
//    exactly one wave, no wave transitions, no tail imbalance.

#define L_DIM    100
#define ROW_F4   1600            // 6400 floats / 4
#define THREADS  320
#define COLBLKS  5               // 5 * 320 = 1600 float4 per row
#define UNROLL   8
#define RGROUPS  (8192 / UNROLL) // 1024 row-groups
#define WORK     (COLBLKS * RGROUPS)  // 5120 work items
#define GRID     (148 * 6)       // one full wave at 6 blocks/SM

__global__ __launch_bounds__(THREADS, 6)
void chem_embed_kernel(const float* __restrict__ x,
                       const float* __restrict__ W,
                       float* __restrict__ out)
{
    const int t = threadIdx.x;

    for (int w = blockIdx.x; w < WORK; w += GRID) {
        const int cb = w % COLBLKS;          // column-group
        const int g  = w / COLBLKS;          // row-group, [0,1024)
        const int b0 = g * UNROLL;           // first batch row

        const int r = cb * THREADS + t;      // float4 column, [0,1600)
        const int i = r >> 4;                // position index (16 float4 each)

        const float4 w4 = __ldg(&((const float4*)W)[r]);   // L1-resident after wave-up

        // 8 independent x loads; single base, immediate offsets u*L_DIM.
        const float* __restrict__ xb = x + (long long)b0 * L_DIM + i;
        float xv[UNROLL];
#pragma unroll
        for (int u = 0; u < UNROLL; u++)
            xv[u] = __ldg(xb + u * L_DIM);

        // 8 independent streaming STG.128; single base, immediate offsets u*ROW_F4.
        float4* __restrict__ ob = ((float4*)out) + (long long)b0 * ROW_F4 + r;
#pragma unroll
        for (int u = 0; u < UNROLL; u++) {
            float4 o;
            o.x = xv[u] * w4.x;
            o.y = xv[u] * w4.y;
            o.z = xv[u] * w4.z;
            o.w = xv[u] * w4.w;
            __stcs(ob + u * ROW_F4, o);
        }
    }
}

extern "C" void kernel_launch(void* const* d_in, const int* in_sizes, int n_in,
                              void* d_out, int out_size)
{
    const float* x = (const float*)d_in[0];   // [8192, 100]
    const float* W = (const float*)d_in[1];   // [100, 64]
    float* out = (float*)d_out;               // [8192, 1, 6400]

    chem_embed_kernel<<<GRID, THREADS>>>(x, W, out);
}

// round 11
// speedup vs baseline: 1.0975x; 1.0625x over previous
#include <cuda_runtime.h>
#include <cuda_bf16.h>

// out[b, i*64 + j] = x[b, i] * W[i, j]
// B=8192, L=100, E=64. Output row = 6400 floats = 1600 float4.
//
// R10: R6's winning memory pattern (UNROLL 8 across strided batch rows,
// __stcs streaming stores, oversubscribed grid) re-tiled onto 256-thread
// blocks at __launch_bounds__(256,8) -> 64 warps/SM = 100% theoretical occ
// (320-thread blocks capped at 60/64). Work flattened over (row-group,
// column): w -> r = w % 1600, b0 = w / 1600. 1600 % 32 == 0 so no warp
// straddles a row: stores stay perfectly coalesced, x-loads broadcast.

#define L_DIM    100
#define ROW_F4   1600            // 6400 floats / 4
#define THREADS  256
#define UNROLL   8
#define BROWS    1024            // 8192 / 8: row-group count; rows b0 + u*1024
#define WORK     (ROW_F4 * BROWS)       // 1,638,400 threads of work
#define GRID     (WORK / THREADS)       // 6400 blocks

__global__ __launch_bounds__(THREADS, 8)
void chem_embed_kernel(const float* __restrict__ x,
                       const float* __restrict__ W,
                       float* __restrict__ out)
{
    const int w  = blockIdx.x * THREADS + threadIdx.x;
    const int r  = w % ROW_F4;           // float4 column, [0,1600)
    const int b0 = w / ROW_F4;           // base batch row, [0,1024)
    const int i  = r >> 4;               // position index (16 float4 each)

    const float4 w4 = __ldg(&((const float4*)W)[r]);

    // 8 independent x loads (rows b0, b0+1024, ..., b0+7168)
    float xv[UNROLL];
#pragma unroll
    for (int u = 0; u < UNROLL; u++)
        xv[u] = __ldg(&x[(long long)(b0 + u * BROWS) * L_DIM + i]);

    // 8 independent fully-coalesced streaming STG.128
#pragma unroll
    for (int u = 0; u < UNROLL; u++) {
        float4 o;
        o.x = xv[u] * w4.x;
        o.y = xv[u] * w4.y;
        o.z = xv[u] * w4.z;
        o.w = xv[u] * w4.w;
        __stcs(((float4*)out) + (long long)(b0 + u * BROWS) * ROW_F4 + r, o);
    }
}

extern "C" void kernel_launch(void* const* d_in, const int* in_sizes, int n_in,
                              void* d_out, int out_size)
{
    const float* x = (const float*)d_in[0];   // [8192, 100]
    const float* W = (const float*)d_in[1];   // [100, 64]
    float* out = (float*)d_out;               // [8192, 1, 6400]

    chem_embed_kernel<<<GRID, THREADS>>>(x, W, out);
}